// round 3
// baseline (speedup 1.0000x reference)
#include <cuda_runtime.h>

#define NTOT       1572864      // 3 * 32 * 128 * 128 scores
#define NQ         393216       // NTOT / 4
#define W_DIM      128
#define H_DIM      128
#define CH_STRIDE  524288       // 32*128*128 (per-channel stride)
#define PRE_N      2000
#define POST_N     300
#define CAND_CAP   4096
#define NMS_T      0.7f
#define CACHE_N    640          // mask rows cached in smem for reduce

// ---------------- scratch (device globals; zero-initialized at load) -------
__device__ unsigned g_hist1[65536];
__device__ unsigned g_hist2[65536];
__device__ unsigned g_prefix;
__device__ unsigned g_above1;
__device__ unsigned g_thresh;
__device__ unsigned g_candCount;   // zeroed by k_scan2 each replay (init 0)
__device__ unsigned long long g_cand[CAND_CAP];
__device__ int g_topIdx[PRE_N];

__device__ float g_bx1[PRE_N], g_by1[PRE_N], g_bz1[PRE_N];
__device__ float g_bx2[PRE_N], g_by2[PRE_N], g_bz2[PRE_N];
__device__ float g_vol[PRE_N], g_sc[PRE_N];

__device__ unsigned g_supp32[64];                 // initial suppression bits (invalid)
__device__ unsigned long long g_mask[PRE_N * 32]; // NMS suppression bitmask rows
__device__ int g_keepList[POST_N];
__device__ int g_keptCount;

__device__ __forceinline__ unsigned mapKey(float f) {
    unsigned b = __float_as_uint(f);
    return b ^ ((b & 0x80000000u) ? 0xFFFFFFFFu : 0x80000000u);
}

// ---------------- top-k: two-level radix select -----------------------------
__global__ void k_hist1(const float4* __restrict__ sc) {
    int t = blockIdx.x * blockDim.x + threadIdx.x;   // 0..NQ-1 exactly
    float4 v = __ldg(&sc[t]);
    atomicAdd(&g_hist1[mapKey(v.x) >> 16], 1u);
    atomicAdd(&g_hist1[mapKey(v.y) >> 16], 1u);
    atomicAdd(&g_hist1[mapKey(v.z) >> 16], 1u);
    atomicAdd(&g_hist1[mapKey(v.w) >> 16], 1u);
}

// find coarse bucket containing rank PRE_N (from top); self-zero hist1
__global__ void k_scan1() {
    __shared__ unsigned a[1024];
    __shared__ unsigned partS[1024];
    int t = threadIdx.x;
    int base = t * 64;
    unsigned s = 0;
    #pragma unroll 8
    for (int i = 0; i < 64; i++) s += g_hist1[base + i];
    partS[t] = s; a[t] = s;
    __syncthreads();
    #pragma unroll
    for (int off = 1; off < 1024; off <<= 1) {
        unsigned v = (t + off < 1024) ? a[t + off] : 0u;
        __syncthreads();
        a[t] += v;
        __syncthreads();
    }
    unsigned sa = a[t] - partS[t];                    // count strictly above my 64 bins
    if (sa < PRE_N && sa + partS[t] >= PRE_N) {
        unsigned run = sa;
        for (int i = 63; i >= 0; i--) {
            unsigned h = g_hist1[base + i];
            run += h;
            if (run >= PRE_N) { g_prefix = (unsigned)(base + i); g_above1 = run - h; break; }
        }
    }
    __syncthreads();
    #pragma unroll 8
    for (int i = 0; i < 64; i++) g_hist1[base + i] = 0u;   // ready for next replay
}

__global__ void k_hist2(const float4* __restrict__ sc) {
    unsigned p = g_prefix;
    int t = blockIdx.x * blockDim.x + threadIdx.x;
    float4 v = __ldg(&sc[t]);
    unsigned kx = mapKey(v.x), ky = mapKey(v.y), kz = mapKey(v.z), kw = mapKey(v.w);
    if ((kx >> 16) == p) atomicAdd(&g_hist2[kx & 0xFFFFu], 1u);
    if ((ky >> 16) == p) atomicAdd(&g_hist2[ky & 0xFFFFu], 1u);
    if ((kz >> 16) == p) atomicAdd(&g_hist2[kz & 0xFFFFu], 1u);
    if ((kw >> 16) == p) atomicAdd(&g_hist2[kw & 0xFFFFu], 1u);
}

// find exact 32-bit threshold; self-zero hist2 and candCount
__global__ void k_scan2() {
    __shared__ unsigned a[1024];
    __shared__ unsigned partS[1024];
    int t = threadIdx.x;
    int base = t * 64;
    unsigned need = PRE_N - g_above1;                 // > 0 by construction
    unsigned s = 0;
    #pragma unroll 8
    for (int i = 0; i < 64; i++) s += g_hist2[base + i];
    partS[t] = s; a[t] = s;
    __syncthreads();
    #pragma unroll
    for (int off = 1; off < 1024; off <<= 1) {
        unsigned v = (t + off < 1024) ? a[t + off] : 0u;
        __syncthreads();
        a[t] += v;
        __syncthreads();
    }
    unsigned sa = a[t] - partS[t];
    if (sa < need && sa + partS[t] >= need) {
        unsigned run = sa;
        for (int i = 63; i >= 0; i--) {
            unsigned h = g_hist2[base + i];
            run += h;
            if (run >= need) { g_thresh = (g_prefix << 16) | (unsigned)(base + i); break; }
        }
    }
    __syncthreads();
    #pragma unroll 8
    for (int i = 0; i < 64; i++) g_hist2[base + i] = 0u;
    if (t == 0) g_candCount = 0u;
}

// collect candidates with key >= thresh, recording TRANSPOSED index (pos*3+a)
__global__ void k_collect(const float4* __restrict__ sc) {
    unsigned T = g_thresh;
    int t = blockIdx.x * blockDim.x + threadIdx.x;
    float4 v = __ldg(&sc[t]);
    int base = 4 * t;
    int a = base / CH_STRIDE;            // all 4 elements share the channel
    int pos = base - a * CH_STRIDE;
    unsigned k0 = mapKey(v.x), k1 = mapKey(v.y), k2 = mapKey(v.z), k3 = mapKey(v.w);
    if (k0 >= T) { unsigned p = atomicAdd(&g_candCount, 1u); if (p < CAND_CAP) g_cand[p] = ((unsigned long long)(~k0) << 32) | (unsigned)((pos + 0) * 3 + a); }
    if (k1 >= T) { unsigned p = atomicAdd(&g_candCount, 1u); if (p < CAND_CAP) g_cand[p] = ((unsigned long long)(~k1) << 32) | (unsigned)((pos + 1) * 3 + a); }
    if (k2 >= T) { unsigned p = atomicAdd(&g_candCount, 1u); if (p < CAND_CAP) g_cand[p] = ((unsigned long long)(~k2) << 32) | (unsigned)((pos + 2) * 3 + a); }
    if (k3 >= T) { unsigned p = atomicAdd(&g_candCount, 1u); if (p < CAND_CAP) g_cand[p] = ((unsigned long long)(~k3) << 32) | (unsigned)((pos + 3) * 3 + a); }
}

// O(n^2) rank-and-scatter: exact sorted order (score desc, transposed idx asc)
__global__ void k_rank() {
    __shared__ unsigned long long keys[CAND_CAP];
    int t = threadIdx.x;                 // 1024 threads
    unsigned cc = g_candCount; if (cc > CAND_CAP) cc = CAND_CAP;
    for (int i = t; i < (int)cc; i += 1024) keys[i] = g_cand[i];
    __syncthreads();
    for (int i = t; i < (int)cc; i += 1024) {
        unsigned long long k = keys[i];
        int r = 0;
        #pragma unroll 8
        for (int j = 0; j < (int)cc; j++) r += (keys[j] < k);
        if (r < PRE_N) g_topIdx[r] = (int)(k & 0xFFFFFFFFu);
    }
}

__global__ void k_transform(const float* __restrict__ sc,
                            const float* __restrict__ dl,
                            const float* __restrict__ imi,
                            const float* __restrict__ anc) {
    int r = blockIdx.x * blockDim.x + threadIdx.x;    // grid covers 2048
    bool valid = false;
    if (r < PRE_N) {
        int idx = g_topIdx[r];            // transposed flat index
        int a   = idx % 3;
        int pos = idx / 3;
        int wl  = pos % W_DIM;
        int hl  = (pos / W_DIM) % H_DIM;
        int sl  = pos / (W_DIM * H_DIM);
        float shx = wl * 4.0f, shy = hl * 4.0f, shz = sl * 4.0f;
        float ax1 = anc[a*6+0] + shx, ay1 = anc[a*6+1] + shy, az1 = anc[a*6+2] + shz;
        float ax2 = anc[a*6+3] + shx, ay2 = anc[a*6+4] + shy, az2 = anc[a*6+5] + shz;

        const float* db = dl + (size_t)(6 * a) * CH_STRIDE + pos;
        float d0 = db[0];
        float d1 = db[(size_t)CH_STRIDE];
        float d2 = db[(size_t)2 * CH_STRIDE];
        float d3 = db[(size_t)3 * CH_STRIDE];
        float d4 = db[(size_t)4 * CH_STRIDE];
        float d5 = db[(size_t)5 * CH_STRIDE];

        float w_ = ax2 - ax1 + 1.0f, h_ = ay2 - ay1 + 1.0f, dd = az2 - az1 + 1.0f;
        float cx = ax1 + 0.5f * w_, cy = ay1 + 0.5f * h_, cz = az1 + 0.5f * dd;
        float pcx = d0 * w_ + cx, pcy = d1 * h_ + cy, pcz = d2 * dd + cz;
        float pw = expf(d3) * w_, ph = expf(d4) * h_, pd = expf(d5) * dd;

        float slices = imi[0], height = imi[1], width = imi[2], scale = imi[3];
        float x1 = fminf(fmaxf(pcx - 0.5f * pw, 0.0f), width  - 1.0f);
        float y1 = fminf(fmaxf(pcy - 0.5f * ph, 0.0f), height - 1.0f);
        float z1 = fminf(fmaxf(pcz - 0.5f * pd, 0.0f), slices - 1.0f);
        float x2 = fminf(fmaxf(pcx + 0.5f * pw - 1.0f, 0.0f), width  - 1.0f);
        float y2 = fminf(fmaxf(pcy + 0.5f * ph - 1.0f, 0.0f), height - 1.0f);
        float z2 = fminf(fmaxf(pcz + 0.5f * pd - 1.0f, 0.0f), slices - 1.0f);

        g_bx1[r] = x1; g_by1[r] = y1; g_bz1[r] = z1;
        g_bx2[r] = x2; g_by2[r] = y2; g_bz2[r] = z2;
        g_vol[r] = (x2 - x1 + 1.0f) * (y2 - y1 + 1.0f) * (z2 - z1 + 1.0f);
        g_sc[r]  = sc[(size_t)a * CH_STRIDE + pos];

        float ss = x2 - x1 + 1.0f;
        float xc = x1 + ss * 0.5f, yc = y1 + ss * 0.5f, zc = z1 + ss * 0.5f;
        valid = (ss >= 8.0f * scale) && (xc < width) && (yc < height) && (zc < slices);
    }
    unsigned suppressed = __ballot_sync(0xFFFFFFFFu, !valid);
    if ((threadIdx.x & 31) == 0) g_supp32[r >> 5] = suppressed;
}

// 64x64-tile suppression bitmask; bit set iff (iou > 0.7) && (j > i)
__global__ void k_mask() {
    int by = blockIdx.y, bx = blockIdx.x;
    int t = threadIdx.x;
    if (bx < by) {
        int i = by * 64 + t;
        if (i < PRE_N) g_mask[(size_t)i * 32 + bx] = 0ULL;
        return;
    }
    __shared__ float cx1[64], cy1[64], cz1[64], cx2[64], cy2[64], cz2[64], cv[64];
    int j = bx * 64 + t;
    if (j < PRE_N) {
        cx1[t] = g_bx1[j]; cy1[t] = g_by1[j]; cz1[t] = g_bz1[j];
        cx2[t] = g_bx2[j]; cy2[t] = g_by2[j]; cz2[t] = g_bz2[j];
        cv[t]  = g_vol[j];
    }
    __syncthreads();
    int i = by * 64 + t;
    if (i >= PRE_N) return;
    float x1 = g_bx1[i], y1 = g_by1[i], z1 = g_bz1[i];
    float x2 = g_bx2[i], y2 = g_by2[i], z2 = g_bz2[i];
    float v  = g_vol[i];
    unsigned long long m = 0ULL;
    int jmax = PRE_N - bx * 64; if (jmax > 64) jmax = 64;
    for (int c = 0; c < jmax; c++) {
        int jg = bx * 64 + c;
        if (jg <= i) continue;
        float iw = fmaxf(fminf(x2, cx2[c]) - fmaxf(x1, cx1[c]) + 1.0f, 0.0f);
        float ih = fmaxf(fminf(y2, cy2[c]) - fmaxf(y1, cy1[c]) + 1.0f, 0.0f);
        float id = fmaxf(fminf(z2, cz2[c]) - fmaxf(z1, cz1[c]) + 1.0f, 0.0f);
        float inter = iw * ih * id;
        float iou = inter / (v + cv[c] - inter);
        if (iou > NMS_T) m |= (1ULL << c);
    }
    g_mask[(size_t)i * 32 + bx] = m;
}

// greedy reduce: first CACHE_N mask rows staged into smem; 1-warp serial chain
__global__ void k_reduce() {
    extern __shared__ unsigned long long rowsSm[];    // CACHE_N * 32
    int t = threadIdx.x;                              // 1024 threads
    for (int w = t; w < CACHE_N * 32; w += 1024) rowsSm[w] = g_mask[w];
    __syncthreads();
    if (t < 32) {
        int lane = t;
        unsigned long long remv =
            ((unsigned long long)g_supp32[2 * lane + 1] << 32) | g_supp32[2 * lane];
        int kept = 0;
        for (int i = 0; i < PRE_N; i++) {
            unsigned long long w = __shfl_sync(0xFFFFFFFFu, remv, i >> 6);
            if (!((w >> (i & 63)) & 1ULL)) {
                remv |= (i < CACHE_N) ? rowsSm[i * 32 + lane]
                                      : g_mask[(size_t)i * 32 + lane];
                if (lane == 0) g_keepList[kept] = i;
                kept++;
                if (kept == POST_N) break;
            }
        }
        if (lane == 0) g_keptCount = kept;
    }
}

__global__ void k_out(float* __restrict__ out, int out_size) {
    int s = blockIdx.x * blockDim.x + threadIdx.x;
    if (s >= POST_N) return;
    int kc = g_keptCount;
    float b0, b1, b2, b3, b4, b5, scv, kidx, vld;
    if (s < kc) {
        int i = g_keepList[s];
        b0 = g_bx1[i]; b1 = g_by1[i]; b2 = g_bz1[i];
        b3 = g_bx2[i]; b4 = g_by2[i]; b5 = g_bz2[i];
        scv = g_sc[i]; kidx = (float)g_topIdx[i]; vld = 1.0f;
    } else {
        b0 = b1 = b2 = b3 = b4 = b5 = 0.0f;
        scv = 0.0f; kidx = -1.0f; vld = 0.0f;
    }
    int base = s * 7;
    out[base + 0] = 0.0f;
    out[base + 1] = b0; out[base + 2] = b1; out[base + 3] = b2;
    out[base + 4] = b3; out[base + 5] = b4; out[base + 6] = b5;
    if (out_size >= POST_N * 7 + POST_N) out[POST_N * 7 + s] = scv;
    if (out_size >= POST_N * 8 + POST_N) out[POST_N * 8 + s] = kidx;
    if (out_size >= POST_N * 9 + POST_N) out[POST_N * 9 + s] = vld;
}

// ---------------- launcher --------------------------------------------------
extern "C" void kernel_launch(void* const* d_in, const int* in_sizes, int n_in,
                              void* d_out, int out_size) {
    const float*  sc  = (const float*)d_in[0];
    const float4* sc4 = (const float4*)d_in[0];
    const float*  dl  = (const float*)d_in[1];
    const float*  imi = (const float*)d_in[2];
    const float*  anc = (const float*)d_in[3];
    float* out = (float*)d_out;

    cudaFuncSetAttribute(k_reduce, cudaFuncAttributeMaxDynamicSharedMemorySize,
                         CACHE_N * 32 * (int)sizeof(unsigned long long));

    k_hist1  <<<NQ / 256, 256>>>(sc4);
    k_scan1  <<<1, 1024>>>();
    k_hist2  <<<NQ / 256, 256>>>(sc4);
    k_scan2  <<<1, 1024>>>();
    k_collect<<<NQ / 256, 256>>>(sc4);
    k_rank   <<<1, 1024>>>();
    k_transform<<<8, 256>>>(sc, dl, imi, anc);
    k_mask   <<<dim3(32, 32), 64>>>();
    k_reduce <<<1, 1024, CACHE_N * 32 * sizeof(unsigned long long)>>>();
    k_out    <<<2, 256>>>(out, out_size);
}

// round 6
// speedup vs baseline: 2.2053x; 2.2053x over previous
#include <cuda_runtime.h>

#define NTOT       1572864      // 3 * 32 * 128 * 128 scores
#define NQ         393216       // NTOT / 4
#define W_DIM      128
#define H_DIM      128
#define CH_STRIDE  524288       // 32*128*128 (per-channel stride)
#define PRE_N      2000
#define POST_N     300
#define CAND_CAP   4096
#define NMS_T      0.7f
#define CACHE_N    640          // mask rows cached in smem for reduce
#define HBINS      262144       // 2^18 coarse bins
#define BIN_SHIFT  14           // key >> 14 -> bin

// ---------------- scratch (device globals; zero-initialized at load) -------
__device__ unsigned g_hist[HBINS];
__device__ unsigned g_thresh;      // key threshold = boundary_bin << BIN_SHIFT
__device__ unsigned g_candCount;
__device__ unsigned long long g_cand[CAND_CAP];
__device__ int g_topIdx[PRE_N];

__device__ float g_bx1[PRE_N], g_by1[PRE_N], g_bz1[PRE_N];
__device__ float g_bx2[PRE_N], g_by2[PRE_N], g_bz2[PRE_N];
__device__ float g_vol[PRE_N], g_sc[PRE_N];

__device__ unsigned g_supp32[64];                 // initial suppression bits
__device__ unsigned long long g_mask[PRE_N * 32]; // NMS suppression bitmask rows
__device__ int g_keepList[POST_N];
__device__ int g_keptCount;

__device__ __forceinline__ unsigned mapKey(float f) {
    unsigned b = __float_as_uint(f);
    return b ^ ((b & 0x80000000u) ? 0xFFFFFFFFu : 0x80000000u);
}

// ---------------- 1) coarse 18-bit histogram --------------------------------
__global__ void k_hist(const float4* __restrict__ sc) {
    int t = blockIdx.x * blockDim.x + threadIdx.x;   // 0..NQ-1 exactly
    float4 v = __ldg(&sc[t]);
    atomicAdd(&g_hist[mapKey(v.x) >> BIN_SHIFT], 1u);
    atomicAdd(&g_hist[mapKey(v.y) >> BIN_SHIFT], 1u);
    atomicAdd(&g_hist[mapKey(v.z) >> BIN_SHIFT], 1u);
    atomicAdd(&g_hist[mapKey(v.w) >> BIN_SHIFT], 1u);
}

// ---------------- 2) find boundary bin (coalesced, warp-segmented) ----------
__global__ void k_scan() {
    __shared__ unsigned warpTot[32];
    __shared__ unsigned suffAbove[32];
    __shared__ int boundWarp;
    int t = threadIdx.x;             // 1024 threads = 32 warps
    int w = t >> 5, l = t & 31;
    if (t == 0) { g_candCount = 0u; boundWarp = -1; }
    int seg = w * 8192;              // warp w owns bins [seg, seg+8192)
    unsigned s = 0;
    #pragma unroll 16
    for (int i = 0; i < 256; i++) s += g_hist[seg + i * 32 + l];   // coalesced
    #pragma unroll
    for (int d = 16; d > 0; d >>= 1) s += __shfl_down_sync(0xFFFFFFFFu, s, d);
    if (l == 0) warpTot[w] = s;
    __syncthreads();
    if (w == 0) {
        unsigned tot = warpTot[l];
        // suffix of totals strictly above warp l (warps l+1..31)
        unsigned suf = tot;
        #pragma unroll
        for (int d = 1; d < 32; d <<= 1) {
            unsigned v = __shfl_down_sync(0xFFFFFFFFu, suf, d);
            if (l + d < 32) suf += v;
        }
        unsigned above = suf - tot;
        if (above < PRE_N && suf >= PRE_N) { boundWarp = l; suffAbove[l] = above; }
    }
    __syncthreads();
    if (w == boundWarp) {
        unsigned running = suffAbove[w];
        for (int c = 255; c >= 0; c--) {
            unsigned h = g_hist[seg + c * 32 + l];
            unsigned suf = h;                 // suffix over lanes >= l
            #pragma unroll
            for (int d = 1; d < 32; d <<= 1) {
                unsigned v = __shfl_down_sync(0xFFFFFFFFu, suf, d);
                if (l + d < 32) suf += v;
            }
            unsigned bal = __ballot_sync(0xFFFFFFFFu, running + suf >= PRE_N);
            if (bal) {
                if (l == 0) {
                    int lb = 31 - __clz(bal);          // highest qualifying lane
                    unsigned bin = (unsigned)(seg + c * 32 + lb);
                    g_thresh = bin << BIN_SHIFT;
                }
                break;
            }
            running += __shfl_sync(0xFFFFFFFFu, suf, 0);   // whole-chunk total
        }
    }
}

// ---------------- 3) collect candidates (transposed idx = pos*3 + a) --------
__global__ void k_collect(const float4* __restrict__ sc) {
    unsigned T = g_thresh;
    int t = blockIdx.x * blockDim.x + threadIdx.x;
    float4 v = __ldg(&sc[t]);
    int base = 4 * t;
    int a = base / CH_STRIDE;            // all 4 elements share the channel
    int pos = base - a * CH_STRIDE;
    unsigned k0 = mapKey(v.x), k1 = mapKey(v.y), k2 = mapKey(v.z), k3 = mapKey(v.w);
    if (k0 >= T) { unsigned p = atomicAdd(&g_candCount, 1u); if (p < CAND_CAP) g_cand[p] = ((unsigned long long)(~k0) << 32) | (unsigned)((pos + 0) * 3 + a); }
    if (k1 >= T) { unsigned p = atomicAdd(&g_candCount, 1u); if (p < CAND_CAP) g_cand[p] = ((unsigned long long)(~k1) << 32) | (unsigned)((pos + 1) * 3 + a); }
    if (k2 >= T) { unsigned p = atomicAdd(&g_candCount, 1u); if (p < CAND_CAP) g_cand[p] = ((unsigned long long)(~k2) << 32) | (unsigned)((pos + 2) * 3 + a); }
    if (k3 >= T) { unsigned p = atomicAdd(&g_candCount, 1u); if (p < CAND_CAP) g_cand[p] = ((unsigned long long)(~k3) << 32) | (unsigned)((pos + 3) * 3 + a); }
}

// ---------------- 4) rank-and-scatter (exact order), 32 blocks --------------
__global__ void k_rank() {
    __shared__ unsigned long long keys[CAND_CAP];
    int t = threadIdx.x;                 // 128 threads
    int cc = (int)g_candCount; if (cc > CAND_CAP) cc = CAND_CAP;
    for (int i = t; i < cc; i += 128) keys[i] = g_cand[i];
    __syncthreads();
    int i = blockIdx.x * 128 + t;        // 4096 threads total: 1 key each
    if (i >= cc) return;
    unsigned long long k = keys[i];
    int r = 0;
    int j = 0;
    for (; j + 4 <= cc; j += 4) {
        r += (keys[j]     < k);
        r += (keys[j + 1] < k);
        r += (keys[j + 2] < k);
        r += (keys[j + 3] < k);
    }
    for (; j < cc; j++) r += (keys[j] < k);
    if (r < PRE_N) g_topIdx[r] = (int)(k & 0xFFFFFFFFu);
}

// ---------------- 5) box decode + validity ----------------------------------
__global__ void k_transform(const float* __restrict__ sc,
                            const float* __restrict__ dl,
                            const float* __restrict__ imi,
                            const float* __restrict__ anc) {
    int r = blockIdx.x * blockDim.x + threadIdx.x;    // grid covers 2048
    bool valid = false;
    if (r < PRE_N) {
        int idx = g_topIdx[r];            // transposed flat index
        int a   = idx % 3;
        int pos = idx / 3;
        int wl  = pos % W_DIM;
        int hl  = (pos / W_DIM) % H_DIM;
        int sl  = pos / (W_DIM * H_DIM);
        float shx = wl * 4.0f, shy = hl * 4.0f, shz = sl * 4.0f;
        float ax1 = anc[a*6+0] + shx, ay1 = anc[a*6+1] + shy, az1 = anc[a*6+2] + shz;
        float ax2 = anc[a*6+3] + shx, ay2 = anc[a*6+4] + shy, az2 = anc[a*6+5] + shz;

        const float* db = dl + (size_t)(6 * a) * CH_STRIDE + pos;
        float d0 = db[0];
        float d1 = db[(size_t)CH_STRIDE];
        float d2 = db[(size_t)2 * CH_STRIDE];
        float d3 = db[(size_t)3 * CH_STRIDE];
        float d4 = db[(size_t)4 * CH_STRIDE];
        float d5 = db[(size_t)5 * CH_STRIDE];

        float w_ = ax2 - ax1 + 1.0f, h_ = ay2 - ay1 + 1.0f, dd = az2 - az1 + 1.0f;
        float cx = ax1 + 0.5f * w_, cy = ay1 + 0.5f * h_, cz = az1 + 0.5f * dd;
        float pcx = d0 * w_ + cx, pcy = d1 * h_ + cy, pcz = d2 * dd + cz;
        float pw = expf(d3) * w_, ph = expf(d4) * h_, pd = expf(d5) * dd;

        float slices = imi[0], height = imi[1], width = imi[2], scale = imi[3];
        float x1 = fminf(fmaxf(pcx - 0.5f * pw, 0.0f), width  - 1.0f);
        float y1 = fminf(fmaxf(pcy - 0.5f * ph, 0.0f), height - 1.0f);
        float z1 = fminf(fmaxf(pcz - 0.5f * pd, 0.0f), slices - 1.0f);
        float x2 = fminf(fmaxf(pcx + 0.5f * pw - 1.0f, 0.0f), width  - 1.0f);
        float y2 = fminf(fmaxf(pcy + 0.5f * ph - 1.0f, 0.0f), height - 1.0f);
        float z2 = fminf(fmaxf(pcz + 0.5f * pd - 1.0f, 0.0f), slices - 1.0f);

        g_bx1[r] = x1; g_by1[r] = y1; g_bz1[r] = z1;
        g_bx2[r] = x2; g_by2[r] = y2; g_bz2[r] = z2;
        g_vol[r] = (x2 - x1 + 1.0f) * (y2 - y1 + 1.0f) * (z2 - z1 + 1.0f);
        g_sc[r]  = sc[(size_t)a * CH_STRIDE + pos];

        float ss = x2 - x1 + 1.0f;
        float xc = x1 + ss * 0.5f, yc = y1 + ss * 0.5f, zc = z1 + ss * 0.5f;
        valid = (ss >= 8.0f * scale) && (xc < width) && (yc < height) && (zc < slices);
    }
    unsigned suppressed = __ballot_sync(0xFFFFFFFFu, !valid);
    if ((threadIdx.x & 31) == 0) g_supp32[r >> 5] = suppressed;
}

// ---------------- 6) IoU suppression bitmask + hist re-zero ------------------
__global__ void k_mask() {
    int by = blockIdx.y, bx = blockIdx.x;
    int t = threadIdx.x;
    // re-zero histogram for the next graph replay (coalesced; 65536 thr x 4)
    {
        int gt = (by * 32 + bx) * 64 + t;
        #pragma unroll
        for (int k = 0; k < 4; k++) g_hist[gt + k * 65536] = 0u;
    }
    if (bx < by) {                       // whole tile has j < i
        int i = by * 64 + t;
        if (i < PRE_N) g_mask[(size_t)i * 32 + bx] = 0ULL;
        return;
    }
    __shared__ float cx1[64], cy1[64], cz1[64], cx2[64], cy2[64], cz2[64], cv[64];
    int j = bx * 64 + t;
    if (j < PRE_N) {
        cx1[t] = g_bx1[j]; cy1[t] = g_by1[j]; cz1[t] = g_bz1[j];
        cx2[t] = g_bx2[j]; cy2[t] = g_by2[j]; cz2[t] = g_bz2[j];
        cv[t]  = g_vol[j];
    }
    __syncthreads();
    int i = by * 64 + t;
    if (i >= PRE_N) return;
    float x1 = g_bx1[i], y1 = g_by1[i], z1 = g_bz1[i];
    float x2 = g_bx2[i], y2 = g_by2[i], z2 = g_bz2[i];
    float v  = g_vol[i];
    unsigned long long m = 0ULL;
    int jmax = PRE_N - bx * 64; if (jmax > 64) jmax = 64;
    for (int c = 0; c < jmax; c++) {
        int jg = bx * 64 + c;
        if (jg <= i) continue;
        float iw = fmaxf(fminf(x2, cx2[c]) - fmaxf(x1, cx1[c]) + 1.0f, 0.0f);
        float ih = fmaxf(fminf(y2, cy2[c]) - fmaxf(y1, cy1[c]) + 1.0f, 0.0f);
        float id = fmaxf(fminf(z2, cz2[c]) - fmaxf(z1, cz1[c]) + 1.0f, 0.0f);
        float inter = iw * ih * id;
        float iou = inter / (v + cv[c] - inter);
        if (iou > NMS_T) m |= (1ULL << c);
    }
    g_mask[(size_t)i * 32 + bx] = m;
}

// ---------------- 7) greedy reduce (smem-cached rows, early exit) -----------
__global__ void k_reduce() {
    extern __shared__ unsigned long long rowsSm[];    // CACHE_N * 32
    int t = threadIdx.x;                              // 1024 threads
    for (int w = t; w < CACHE_N * 32; w += 1024) rowsSm[w] = g_mask[w];
    __syncthreads();
    if (t < 32) {
        int lane = t;
        unsigned long long remv =
            ((unsigned long long)g_supp32[2 * lane + 1] << 32) | g_supp32[2 * lane];
        int kept = 0;
        for (int i = 0; i < PRE_N; i++) {
            unsigned long long w = __shfl_sync(0xFFFFFFFFu, remv, i >> 6);
            if (!((w >> (i & 63)) & 1ULL)) {
                remv |= (i < CACHE_N) ? rowsSm[i * 32 + lane]
                                      : g_mask[(size_t)i * 32 + lane];
                if (lane == 0) g_keepList[kept] = i;
                kept++;
                if (kept == POST_N) break;
            }
        }
        if (lane == 0) g_keptCount = kept;
    }
}

// ---------------- 8) output --------------------------------------------------
__global__ void k_out(float* __restrict__ out, int out_size) {
    int s = blockIdx.x * blockDim.x + threadIdx.x;
    if (s >= POST_N) return;
    int kc = g_keptCount;
    float b0, b1, b2, b3, b4, b5, scv, kidx, vld;
    if (s < kc) {
        int i = g_keepList[s];
        b0 = g_bx1[i]; b1 = g_by1[i]; b2 = g_bz1[i];
        b3 = g_bx2[i]; b4 = g_by2[i]; b5 = g_bz2[i];
        scv = g_sc[i]; kidx = (float)g_topIdx[i]; vld = 1.0f;
    } else {
        b0 = b1 = b2 = b3 = b4 = b5 = 0.0f;
        scv = 0.0f; kidx = -1.0f; vld = 0.0f;
    }
    int base = s * 7;
    out[base + 0] = 0.0f;
    out[base + 1] = b0; out[base + 2] = b1; out[base + 3] = b2;
    out[base + 4] = b3; out[base + 5] = b4; out[base + 6] = b5;
    if (out_size >= POST_N * 7 + POST_N) out[POST_N * 7 + s] = scv;
    if (out_size >= POST_N * 8 + POST_N) out[POST_N * 8 + s] = kidx;
    if (out_size >= POST_N * 9 + POST_N) out[POST_N * 9 + s] = vld;
}

// ---------------- launcher --------------------------------------------------
extern "C" void kernel_launch(void* const* d_in, const int* in_sizes, int n_in,
                              void* d_out, int out_size) {
    const float*  sc  = (const float*)d_in[0];
    const float4* sc4 = (const float4*)d_in[0];
    const float*  dl  = (const float*)d_in[1];
    const float*  imi = (const float*)d_in[2];
    const float*  anc = (const float*)d_in[3];
    float* out = (float*)d_out;

    cudaFuncSetAttribute(k_reduce, cudaFuncAttributeMaxDynamicSharedMemorySize,
                         CACHE_N * 32 * (int)sizeof(unsigned long long));

    k_hist   <<<NQ / 256, 256>>>(sc4);
    k_scan   <<<1, 1024>>>();
    k_collect<<<NQ / 256, 256>>>(sc4);
    k_rank   <<<32, 128>>>();
    k_transform<<<8, 256>>>(sc, dl, imi, anc);
    k_mask   <<<dim3(32, 32), 64>>>();
    k_reduce <<<1, 1024, CACHE_N * 32 * sizeof(unsigned long long)>>>();
    k_out    <<<2, 256>>>(out, out_size);
}